// round 11
// baseline (speedup 1.0000x reference)
#include <cuda_runtime.h>
#include <math.h>

#define NPTS 8192
#define BB   4
#define DD   128
#define KK   8
#define NB   (NPTS*BB)        // 32768
#define NR   (NB*KK)          // 262144

#define THREADS 512

#define WST2 136              // W hi/lo tile word stride (rows = 64 k-pairs)
#define AST2 68               // A hi/lo tile word stride (rows = 128 m)

// smem word offsets
#define OFF_WHI 0             // 64*136  = 8704
#define OFF_WLO 8704
#define OFF_AHI 17408         // 128*68  = 8704
#define OFF_ALO 26112
#define OFF_SB  34816         // bias[128]
#define SMEM_WORDS 34944
#define SMEM_BYTES (SMEM_WORDS*4)   // 139776

// ---------------- scratch ----------------
__device__ float g_qf[BB*NPTS*DD];
__device__ float g_kf[BB*NPTS*DD];
__device__ float g_vf[BB*NPTS*DD];
__device__ float g_res[BB*NPTS*DD];
__device__ int   g_idx[BB*NPTS*KK];
__device__ float g_h [NR*DD];        // h = gelu(lin1(rel)); later reused for logits a
__device__ float g_pe[NR*DD];
__device__ float g_u [NR*DD];

// ---------------- bf16 helpers ----------------
__device__ __forceinline__ unsigned bfpack(float lo_elem, float hi_elem) {
    unsigned r;
    asm("cvt.rn.bf16x2.f32 %0, %1, %2;" : "=r"(r) : "f"(hi_elem), "f"(lo_elem));
    return r;
}
__device__ __forceinline__ void bfsplit(float x0, float x1,
                                        unsigned& hp, unsigned& lp) {
    hp = bfpack(x0, x1);
    float h0 = __uint_as_float(hp << 16);
    float h1 = __uint_as_float(hp & 0xFFFF0000u);
    lp = bfpack(x0 - h0, x1 - h1);
}
__device__ __forceinline__ void mma_bf16(float* c, const unsigned* a,
                                         unsigned b0, unsigned b1) {
    asm volatile(
        "mma.sync.aligned.m16n8k16.row.col.f32.bf16.bf16.f32 "
        "{%0,%1,%2,%3}, {%4,%5,%6,%7}, {%8,%9}, {%0,%1,%2,%3};"
        : "+f"(c[0]), "+f"(c[1]), "+f"(c[2]), "+f"(c[3])
        : "r"(a[0]), "r"(a[1]), "r"(a[2]), "r"(a[3]), "r"(b0), "r"(b1));
}

// ============================================================================
// bf16-split MMA GEMM, persistent tile loop, 512 threads (R10 verbatim).
// ============================================================================
__global__ __launch_bounds__(THREADS, 1) void gemm_mma(
    const float* __restrict__ Aext, const float* __restrict__ W,
    const float* __restrict__ bias, const float* __restrict__ resid,
    float* __restrict__ outext, int ntiles, int mode)
{
    extern __shared__ unsigned smw[];
    unsigned* WhiP = smw + OFF_WHI;
    unsigned* WloP = smw + OFF_WLO;
    unsigned* AhiP = smw + OFF_AHI;
    unsigned* AloP = smw + OFF_ALO;
    float* sb = (float*)(smw + OFF_SB);

    const int tid = threadIdx.x;

    #pragma unroll
    for (int p = tid; p < 2048; p += THREADS) {
        int kk = p >> 5, nq = p & 31;
        const float4 L0 = *(const float4*)(W + (2*kk    )*128 + 4*nq);
        const float4 L1 = *(const float4*)(W + (2*kk + 1)*128 + 4*nq);
        uint4 h, l;
        bfsplit(L0.x, L1.x, h.x, l.x);
        bfsplit(L0.y, L1.y, h.y, l.y);
        bfsplit(L0.z, L1.z, h.z, l.z);
        bfsplit(L0.w, L1.w, h.w, l.w);
        *(uint4*)(WhiP + kk*WST2 + 4*nq) = h;
        *(uint4*)(WloP + kk*WST2 + 4*nq) = l;
    }
    if (tid < 128) sb[tid] = bias[tid];

    const float* Aptr = (mode == 3) ? (const float*)g_res :
                        (mode == 4) ? (const float*)g_h  :
                        (mode == 5) ? (const float*)g_u  : Aext;

    const int lane  = tid & 31;
    const int wid   = tid >> 5;
    const int warpM = (wid & 3) * 32;
    const int warpN = (wid >> 2) * 32;
    const int gid   = lane >> 2;
    const int tig   = lane & 3;

    for (int tile = blockIdx.x; tile < ntiles; tile += gridDim.x) {
        const int m0 = tile * 128;

        __syncthreads();
        #pragma unroll
        for (int i = tid; i < 4096; i += THREADS) {
            int m = i >> 5, cc = i & 31;
            int gm = m0 + m;
            int arow = (mode == 3) ? ((gm & 3) * NPTS + (gm >> 2)) : gm;
            float4 v = *(const float4*)(Aptr + (size_t)arow*DD + cc*4);
            uint2 h, l;
            bfsplit(v.x, v.y, h.x, l.x);
            bfsplit(v.z, v.w, h.y, l.y);
            *(uint2*)(AhiP + m*AST2 + 2*cc) = h;
            *(uint2*)(AloP + m*AST2 + 2*cc) = l;
        }
        __syncthreads();

        float acc[2][4][4];
        #pragma unroll
        for (int mt = 0; mt < 2; mt++)
            #pragma unroll
            for (int nt = 0; nt < 4; nt++)
                #pragma unroll
                for (int q = 0; q < 4; q++) acc[mt][nt][q] = 0.f;

        #pragma unroll 1
        for (int ks = 0; ks < 8; ++ks) {
            const int kk0 = ks * 8;
            unsigned ahi[2][4], alo[2][4];
            #pragma unroll
            for (int mt = 0; mt < 2; mt++) {
                const int r0 = warpM + mt*16 + gid;
                ahi[mt][0] = AhiP[(r0    )*AST2 + kk0 + tig];
                ahi[mt][1] = AhiP[(r0 + 8)*AST2 + kk0 + tig];
                ahi[mt][2] = AhiP[(r0    )*AST2 + kk0 + tig + 4];
                ahi[mt][3] = AhiP[(r0 + 8)*AST2 + kk0 + tig + 4];
                alo[mt][0] = AloP[(r0    )*AST2 + kk0 + tig];
                alo[mt][1] = AloP[(r0 + 8)*AST2 + kk0 + tig];
                alo[mt][2] = AloP[(r0    )*AST2 + kk0 + tig + 4];
                alo[mt][3] = AloP[(r0 + 8)*AST2 + kk0 + tig + 4];
            }
            #pragma unroll
            for (int nt = 0; nt < 4; nt++) {
                const int nc = warpN + nt*8 + gid;
                unsigned bh0 = WhiP[(kk0 + tig    )*WST2 + nc];
                unsigned bh1 = WhiP[(kk0 + tig + 4)*WST2 + nc];
                unsigned bl0 = WloP[(kk0 + tig    )*WST2 + nc];
                unsigned bl1 = WloP[(kk0 + tig + 4)*WST2 + nc];
                #pragma unroll
                for (int mt = 0; mt < 2; mt++) {
                    mma_bf16(acc[mt][nt], ahi[mt], bh0, bh1);
                    mma_bf16(acc[mt][nt], alo[mt], bh0, bh1);
                    mma_bf16(acc[mt][nt], ahi[mt], bl0, bl1);
                }
            }
        }

        #pragma unroll
        for (int mt = 0; mt < 2; mt++) {
            #pragma unroll
            for (int half = 0; half < 2; half++) {
                const int rl = warpM + mt*16 + gid + half*8;
                const int gm = m0 + rl;
                float* orow;
                const float* rrow = 0;
                if (mode == 0)      orow = g_qf + (size_t)((gm & 3)*NPTS + (gm >> 2)) * DD;
                else if (mode == 1) orow = g_kf + (size_t)((gm & 3)*NPTS + (gm >> 2)) * DD;
                else if (mode == 2) orow = g_vf + (size_t)((gm & 3)*NPTS + (gm >> 2)) * DD;
                else if (mode == 3) { orow = outext + (size_t)gm * DD; rrow = resid + (size_t)gm * DD; }
                else if (mode == 4) orow = g_pe + (size_t)gm * DD;
                else                orow = g_h  + (size_t)gm * DD;
                #pragma unroll
                for (int nt = 0; nt < 4; nt++) {
                    const int col = warpN + nt*8 + 2*tig;
                    float2 v;
                    v.x = acc[mt][nt][half*2    ] + sb[col];
                    v.y = acc[mt][nt][half*2 + 1] + sb[col + 1];
                    if (mode == 3) {
                        float2 rr = *(const float2*)(rrow + col);
                        v.x += rr.x; v.y += rr.y;
                    }
                    *(float2*)(orow + col) = v;
                }
            }
        }
    }
}

// ============================================================================
// KNN v5: 8-way split + shift trick + SHARED-MEMORY top-8 lists with a
// dynamic-trip-count insertion loop. The smem stores + runtime while-loop
// cannot be if-converted, so the hot loop is LDS.128 + 3FMA + SETP + rare
// branch instead of a 7-level predicated select chain every iteration.
// ============================================================================
__global__ __launch_bounds__(256, 1) void knn_k(const float* __restrict__ pos)
{
    __shared__ float4 cand[1032];        // 8 chunks of 129 (128 used)
    __shared__ float  sd[256*8];
    __shared__ int    si[256*8];

    const int b = blockIdx.y;
    const int t = threadIdx.x;
    const int q = blockIdx.x * 32 + (t >> 3);
    const int s = t & 7;
    const float* pb = pos + (size_t)b * NPTS * 3;

    const float qx = pb[q*3], qy = pb[q*3+1], qz = pb[q*3+2];
    const float nx = -2.f*qx, ny = -2.f*qy, nz = -2.f*qz;

    float* myd = sd + t*8;
    int*   myi = si + t*8;
    #pragma unroll
    for (int k = 0; k < 8; k++) { myd[k] = 1e30f; myi[k] = 0x7fffffff; }
    float bd7 = 1e30f;

    const int base = s * 129;
    for (int t0 = 0; t0 < NPTS; t0 += 1024) {
        __syncthreads();
        #pragma unroll
        for (int i = t; i < 1024; i += 256) {
            float x = pb[(t0+i)*3], y = pb[(t0+i)*3+1], z = pb[(t0+i)*3+2];
            cand[i + (i >> 7)] = make_float4(x, y, z, fmaf(z, z, fmaf(y, y, x*x)));
        }
        __syncthreads();
        #pragma unroll 4
        for (int m = 0; m < 128; ++m) {
            float4 c = cand[base + m];
            float sv = fmaf(nx, c.x, fmaf(ny, c.y, fmaf(nz, c.z, c.w)));
            if (sv < bd7) {
                // rare slow path: sorted insert into smem list
                int idx = t0 + s*128 + m;
                int r = 7;
                #pragma unroll 1
                while (r > 0 && myd[r-1] > sv) {
                    myd[r] = myd[r-1];
                    myi[r] = myi[r-1];
                    --r;
                }
                myd[r] = sv;
                myi[r] = idx;
                bd7 = myd[7];
            }
        }
    }
    __syncthreads();

    if (s == 0) {
        int p[8] = {0,0,0,0,0,0,0,0};
        int* op = g_idx + ((size_t)b * NPTS + q) * KK;
        #pragma unroll
        for (int o = 0; o < 8; ++o) {
            float bdv = 1e38f; int biv = 0x7fffffff; int bl = 0;
            #pragma unroll
            for (int l = 0; l < 8; ++l) {
                float dv = sd[(t+l)*8 + p[l]];
                int   iv = si[(t+l)*8 + p[l]];
                if (dv < bdv || (dv == bdv && iv < biv)) { bdv = dv; biv = iv; bl = l; }
            }
            op[o] = biv;
            p[bl]++;
        }
    }
}

// ============================================================================
// build h (float4) — R10 verbatim
// ============================================================================
__global__ __launch_bounds__(256, 1) void buildh_k(
    const float* __restrict__ pos,
    const float* __restrict__ Wp1, const float* __restrict__ bp1)
{
    const int gid = blockIdx.x * 256 + threadIdx.x;   // < NR*32
    const int r = gid >> 5, d0 = (gid & 31) * 4;
    const int g = r >> 3;
    const int b = g >> 13, n = g & (NPTS - 1);
    const int id = g_idx[r];
    const float* pb = pos + (size_t)b * NPTS * 3;
    const float rx = pb[n*3+0] - pb[id*3+0];
    const float ry = pb[n*3+1] - pb[id*3+1];
    const float rz = pb[n*3+2] - pb[id*3+2];
    const float4 wx = *(const float4*)(Wp1 + d0);
    const float4 wy = *(const float4*)(Wp1 + 128 + d0);
    const float4 wz = *(const float4*)(Wp1 + 256 + d0);
    const float4 bb = *(const float4*)(bp1 + d0);
    float4 o;
    {
        float z = fmaf(rz, wz.x, fmaf(ry, wy.x, fmaf(rx, wx.x, bb.x)));
        o.x = 0.5f * z * (1.f + erff(z * 0.70710678118654752f));
    }
    {
        float z = fmaf(rz, wz.y, fmaf(ry, wy.y, fmaf(rx, wx.y, bb.y)));
        o.y = 0.5f * z * (1.f + erff(z * 0.70710678118654752f));
    }
    {
        float z = fmaf(rz, wz.z, fmaf(ry, wy.z, fmaf(rx, wx.z, bb.z)));
        o.z = 0.5f * z * (1.f + erff(z * 0.70710678118654752f));
    }
    {
        float z = fmaf(rz, wz.w, fmaf(ry, wy.w, fmaf(rx, wx.w, bb.w)));
        o.w = 0.5f * z * (1.f + erff(z * 0.70710678118654752f));
    }
    *(float4*)(g_h + (size_t)r*DD + d0) = o;
}

// ============================================================================
// build u (float4) — R10 verbatim
// ============================================================================
__global__ __launch_bounds__(256, 1) void buildu_k()
{
    const int gid = blockIdx.x * 256 + threadIdx.x;   // < NR*32
    const int r = gid >> 5, seg = (gid & 31) * 4;
    const int g = r >> 3;
    const int id = g_idx[r];
    const int b = g >> 13;
    float4 qv = *(const float4*)(g_qf + (size_t)g * DD + seg);
    float4 kv = *(const float4*)(g_kf + ((size_t)b * NPTS + id) * DD + seg);
    float4 pe = *(const float4*)(g_pe + (size_t)r * DD + seg);
    float4 u;
    u.x = qv.x - kv.x + pe.x; u.y = qv.y - kv.y + pe.y;
    u.z = qv.z - kv.z + pe.z; u.w = qv.w - kv.w + pe.w;
    *(float4*)(g_u + (size_t)r * DD + seg) = u;
}

// ============================================================================
// finish — R10 verbatim
// ============================================================================
__global__ __launch_bounds__(256, 1) void finish_k()
{
    __shared__ float rA[2][32];
    __shared__ float rB[2][32];

    const int tid  = threadIdx.x;
    const int grp  = tid >> 7;
    const int d    = tid & 127;
    const int lane = tid & 31;
    const int wsub = (tid >> 5) & 3;
    const int g    = blockIdx.x * 2 + grp;
    const int b    = g >> 13;
    const float scale = 0.08838834764831845f;   // 1/sqrt(128)

    float a[8];
    #pragma unroll
    for (int k = 0; k < 8; ++k)
        a[k] = g_h[((size_t)g*8 + k) * DD + d] * scale;

    float red[8];
    #pragma unroll
    for (int k = 0; k < 8; ++k) red[k] = a[k];
    #pragma unroll
    for (int off = 16; off > 0; off >>= 1)
        #pragma unroll
        for (int k = 0; k < 8; ++k)
            red[k] = fmaxf(red[k], __shfl_xor_sync(0xffffffffu, red[k], off));
    if (lane == 0) {
        #pragma unroll
        for (int k = 0; k < 8; ++k) rA[grp][wsub*8 + k] = red[k];
    }
    __syncthreads();

    float e[8];
    #pragma unroll
    for (int k = 0; k < 8; ++k) {
        float bm = fmaxf(fmaxf(rA[grp][k], rA[grp][8+k]),
                         fmaxf(rA[grp][16+k], rA[grp][24+k]));
        e[k] = __expf(a[k] - bm);
        red[k] = e[k];
    }
    #pragma unroll
    for (int off = 16; off > 0; off >>= 1)
        #pragma unroll
        for (int k = 0; k < 8; ++k)
            red[k] += __shfl_xor_sync(0xffffffffu, red[k], off);
    if (lane == 0) {
        #pragma unroll
        for (int k = 0; k < 8; ++k) rB[grp][wsub*8 + k] = red[k];
    }
    __syncthreads();

    float rsum = 0.f;
    #pragma unroll
    for (int k = 0; k < 8; ++k) {
        float tot = (rB[grp][k] + rB[grp][8+k]) + (rB[grp][16+k] + rB[grp][24+k]);
        float smx = e[k] / tot;
        int id = g_idx[(size_t)g*8 + k];
        float v  = g_vf[((size_t)b * NPTS + id) * DD + d];
        float pe = g_pe[((size_t)g*8 + k) * DD + d];
        rsum = fmaf(smx, v + pe, rsum);
    }
    g_res[(size_t)g * DD + d] = rsum;
}

// ============================================================================
// host launch
// ============================================================================
extern "C" void kernel_launch(void* const* d_in, const int* in_sizes, int n_in,
                              void* d_out, int out_size)
{
    const float* query = (const float*)d_in[0];
    const float* pos   = (const float*)d_in[1];
    const float* Wq  = (const float*)d_in[2];  const float* bq  = (const float*)d_in[3];
    const float* Wk  = (const float*)d_in[4];  const float* bk  = (const float*)d_in[5];
    const float* Wv  = (const float*)d_in[6];  const float* bv  = (const float*)d_in[7];
    const float* Wp1 = (const float*)d_in[8];  const float* bp1 = (const float*)d_in[9];
    const float* Wp2 = (const float*)d_in[10]; const float* bp2 = (const float*)d_in[11];
    const float* Wg  = (const float*)d_in[12]; const float* bg  = (const float*)d_in[13];
    const float* Wo  = (const float*)d_in[14]; const float* bo  = (const float*)d_in[15];
    float* out = (float*)d_out;

    cudaFuncSetAttribute(gemm_mma, cudaFuncAttributeMaxDynamicSharedMemorySize, SMEM_BYTES);

    int dev = 0, sms = 148;
    cudaGetDevice(&dev);
    cudaDeviceGetAttribute(&sms, cudaDevAttrMultiProcessorCount, dev);

    const int NT_NB = NB/128;   // 256
    const int NT_NR = NR/128;   // 2048
    const int gNB = (NT_NB < sms) ? NT_NB : sms;
    const int gNR = sms;

    // KNN first (longest independent kernel)
    knn_k<<<dim3(NPTS/32, BB), 256>>>(pos);

    // QKV projections -> g_qf/g_kf/g_vf in [B,N,D]
    gemm_mma<<<gNB, THREADS, SMEM_BYTES>>>(query, Wq, bq, 0, 0, NT_NB, 0);
    gemm_mma<<<gNB, THREADS, SMEM_BYTES>>>(query, Wk, bk, 0, 0, NT_NB, 1);
    gemm_mma<<<gNB, THREADS, SMEM_BYTES>>>(query, Wv, bv, 0, 0, NT_NB, 2);

    // h = gelu(lin1(rel))          [NR,128]
    buildh_k<<<NR*32/256, 256>>>(pos, Wp1, bp1);

    // pe = h @ Wp2 + bp2           [NR,128]
    gemm_mma<<<gNR, THREADS, SMEM_BYTES>>>(0, Wp2, bp2, 0, 0, NT_NR, 4);

    // u = q - k_knn + pe           [NR,128]
    buildu_k<<<NR*32/256, 256>>>();

    // a = u @ Wg + bg              [NR,128]  (into g_h)
    gemm_mma<<<gNR, THREADS, SMEM_BYTES>>>(0, Wg, bg, 0, 0, NT_NR, 5);

    // softmax over d + weighted sum over k -> g_res [B,N,D]
    finish_k<<<NB/2, 256>>>();

    // out = res@Wo + bo + query    [N,B,D]
    gemm_mma<<<gNB, THREADS, SMEM_BYTES>>>(query, Wo, bo, query, out, NT_NB, 3);
}